// round 15
// baseline (speedup 1.0000x reference)
#include <cuda_runtime.h>
#include <math.h>

#define NROWS 500000
#define NA 5
#define TT 8
#define NE 18
#define MB 4
#define EPSV 1e-8f
#define ML2 (0.02f * 0.02f)
#define BLK 128
#define NCLS (NE * MB * TT)   // 576

typedef unsigned long long u64;

__global__ void zero_out_kernel(float* out) { out[0] = 0.0f; }

__device__ __forceinline__ float sqrt_approx(float a) {
    float r; asm("sqrt.approx.f32 %0, %1;" : "=f"(r) : "f"(a)); return r;
}
__device__ __forceinline__ float rcp_approx(float a) {
    float r; asm("rcp.approx.f32 %0, %1;" : "=f"(r) : "f"(a)); return r;
}

// ---- packed f32x2 helpers ----
__device__ __forceinline__ u64 add2(u64 a, u64 b) {
    u64 r; asm("add.rn.f32x2 %0, %1, %2;" : "=l"(r) : "l"(a), "l"(b)); return r;
}
__device__ __forceinline__ u64 mul2(u64 a, u64 b) {
    u64 r; asm("mul.rn.f32x2 %0, %1, %2;" : "=l"(r) : "l"(a), "l"(b)); return r;
}
__device__ __forceinline__ u64 fma2(u64 a, u64 b, u64 c) {
    u64 r; asm("fma.rn.f32x2 %0, %1, %2, %3;" : "=l"(r) : "l"(a), "l"(b), "l"(c)); return r;
}
__device__ __forceinline__ u64 neg2(u64 a) { return a ^ 0x8000000080000000ULL; }
__device__ __forceinline__ void unpack2(u64 v, float& lo, float& hi) {
    asm("mov.b64 {%0, %1}, %2;" : "=f"(lo), "=f"(hi) : "l"(v));
}

// pair index for 5 atoms: (a<b) -> 0..9 ; a==b -> 10 (zero slot)
__device__ __forceinline__ int pidx(int a, int b) {
    if (a == b) return 10;
    int lo = min(a, b), hi = max(a, b);
    return lo * 4 - (lo * (lo - 1)) / 2 + (hi - lo - 1);
}

__global__ void __launch_bounds__(BLK, 8) loss_kernel(
    const float* __restrict__ x,
    const float* __restrict__ yt,
    const float* __restrict__ yp,
    const float* __restrict__ mk,
    const int* __restrict__ trip,
    const int* __restrict__ tvalid,
    float* __restrict__ out)
{
    __shared__ __align__(16) unsigned s_pk[NCLS];    // 2.3 KB
    __shared__ __align__(16) float2  s_tp[BLK * 15]; // staged {t,p}; reused per-thread for pair D^2
    __shared__ float warpsum[BLK / 32];

    const int tid  = threadIdx.x;
    const int lane = tid & 31;
    const int wid  = tid >> 5;
    const int row0 = blockIdx.x * BLK;
    const int cnt  = min(BLK, NROWS - row0);
    const bool live = (tid < cnt);
    const int row  = row0 + tid;

    // -------- mask bits: warp-cooperative ballot transpose (main path) --------
    unsigned mb = 0;
    if (cnt == BLK) {
        // warp's 32 rows cover 480 consecutive mask floats: read coalesced,
        // ballot each 32-chunk, redistribute bits via shuffle.
        const float* gmw = mk + (size_t)(row0 + wid * 32) * 15;
        unsigned myBal = 0;
#pragma unroll
        for (int k = 0; k < 15; k++) {
            float v = gmw[k * 32 + lane];                     // coalesced LDG.32
            unsigned b = __ballot_sync(0xffffffffu, v > 0.0f);
            if (k == lane) myBal = b;                         // lane k keeps ballot k
        }
        const int s  = lane * 15;       // bit offset of this row's 15 bits
        const int w0 = s >> 5;
        const int o  = s & 31;
        unsigned B0 = __shfl_sync(0xffffffffu, myBal, w0);
        unsigned B1 = __shfl_sync(0xffffffffu, myBal, (w0 + 1) & 31);
        mb = B0 >> o;
        if (o) mb |= B1 << (32 - o);
        mb &= 0x7FFFu;
    } else if (live) {
        const float* mrow = mk + (size_t)row * 15;
#pragma unroll
        for (int e = 0; e < 15; e++)
            mb |= (mrow[e] > 0.0f ? 1u : 0u) << e;
    }

    float gate = 0.0f, bd = 0.0f;
    if (live) {
        const float2 xg = *(const float2*)(x + (size_t)row * 38 + 36);
        bd = xg.x; gate = xg.y;
    }

    // -------- pack tables: atom idx (3b x3) + pair idx (4b x3) + ok --------
    for (int e = tid; e < NCLS; e += BLK) {
        const int i0 = trip[3 * e + 0];
        const int i1 = trip[3 * e + 1];
        const int i2 = trip[3 * e + 2];
        const int v  = tvalid[e];
        const unsigned ok = (i0 >= 0 && i1 >= 0 && i2 >= 0 && v > 0) ? 1u : 0u;
        const int ii = max(i0, 0);
        const int jj = max(i1, 0);
        const int kk = max(i2, 0);
        const unsigned p1 = (unsigned)pidx(ii, jj);   // |i-j|^2
        const unsigned p2 = (unsigned)pidx(kk, jj);   // |k-j|^2
        const unsigned p3 = (unsigned)pidx(ii, kk);   // |i-k|^2
        s_pk[e] = (unsigned)ii | ((unsigned)jj << 3) | ((unsigned)kk << 6)
                | (p1 << 9) | (p2 << 13) | (p3 << 17) | (ok << 21);
    }

    // -------- stage y_true/y_pred interleaved --------
    if (cnt == BLK) {
        const float2* gt2 = (const float2*)(yt + (size_t)row0 * 15);
        const float2* gp2 = (const float2*)(yp + (size_t)row0 * 15);
        float4* d4 = (float4*)s_tp;
#pragma unroll
        for (int k = 0; k < 8; k++) {
            int i = tid + k * BLK;
            if (i < 960) {
                float2 a = gt2[i];
                float2 b = gp2[i];
                d4[i] = make_float4(a.x, b.x, a.y, b.y);  // s_tp[2i], s_tp[2i+1]
            }
        }
    } else {
        const int tot = cnt * 15;
        const float* gt = yt + (size_t)row0 * 15;
        const float* gp = yp + (size_t)row0 * 15;
        for (int i = tid; i < tot; i += BLK)
            s_tp[i] = make_float2(gt[i], gp[i]);
    }
    __syncthreads();

    float acc = 0.0f;

    if (live) {
        u64* myp = (u64*)(s_tp + tid * 15);   // thread-PRIVATE slice

        // ---- load own 15 {t,p} u64 into registers ----
        u64 q[15];
#pragma unroll
        for (int c = 0; c < 15; c++) q[c] = myp[c];

        // ---------------- atom MSE (from registers) ----------------
        unsigned avmask = 0;
        float num = 0.0f;
#pragma unroll
        for (int a = 0; a < NA; a++) {
            float t0, p0, t1, p1, t2, p2;
            unpack2(q[3 * a + 0], t0, p0);
            unpack2(q[3 * a + 1], t1, p1);
            unpack2(q[3 * a + 2], t2, p2);
            float d0 = t0 - p0, d1 = t1 - p1, d2 = t2 - p2;
            unsigned g = (mb >> (3 * a)) & 7u;
            num += ((g & 1u) ? d0 * d0 : 0.0f)
                 + ((g & 2u) ? d1 * d1 : 0.0f)
                 + ((g & 4u) ? d2 * d2 : 0.0f);
            avmask |= (g ? 1u : 0u) << a;
        }
        float atom = num * rcp_approx((float)__popc(avmask) + EPSV);

        // ---- precompute 10 packed pair squared-distances into own slice ----
        {
            const int PA[10] = {0,0,0,0,1,1,1,2,2,3};
            const int PB[10] = {1,2,3,4,2,3,4,3,4,4};
#pragma unroll
            for (int pr = 0; pr < 10; pr++) {
                const int a = PA[pr], b = PB[pr];
                u64 dx = add2(q[a * 3 + 0], neg2(q[b * 3 + 0]));
                u64 dy = add2(q[a * 3 + 1], neg2(q[b * 3 + 1]));
                u64 dz = add2(q[a * 3 + 2], neg2(q[b * 3 + 2]));
                myp[pr] = fma2(dz, dz, fma2(dy, dy, mul2(dx, dx)));
            }
            myp[10] = 0ULL;   // zero slot for degenerate pairs
        }

        // ---------------- angle loss via law of cosines ----------------
        if (!isfinite(gate)) gate = 0.0f;
        int rid = (int)rintf(gate) - 1;
        rid = min(max(rid, 0), NE - 1);
        if (!isfinite(bd)) bd = 0.0f;
        int bid = min(max((int)rintf(bd), 0), MB - 1);

        const int base = (rid * MB + bid) * TT;      // multiple of 8 -> 32B aligned
        const uint4* pkp = (const uint4*)(s_pk + base);

        const float lo = -1.0f + 1e-6f, hi = 1.0f - 1e-6f;
        float anum = 0.0f, aden = 0.0f;

#pragma unroll
        for (int h = 0; h < 2; h++) {
            const uint4 pk4 = pkp[h];
            const unsigned pkw[4] = { pk4.x, pk4.y, pk4.z, pk4.w };
#pragma unroll
            for (int e = 0; e < 4; e++) {
                const unsigned pk = pkw[e];
                const int ii = pk & 7;
                const int jj = (pk >> 3) & 7;
                const int kk = (pk >> 6) & 7;
                unsigned okb = (pk >> 21) & (avmask >> ii) & (avmask >> jj) & (avmask >> kk) & 1u;

                // 3 LDS.64: packed {true,pred} pair distances
                u64 L1 = myp[(pk >> 9)  & 15];   // |i-j|^2
                u64 L2 = myp[(pk >> 13) & 15];   // |k-j|^2
                u64 D3 = myp[(pk >> 17) & 15];   // |i-k|^2

                float l1t, l1p, l2t, l2p, d3t, d3p;
                unpack2(L1, l1t, l1p);
                unpack2(L2, l2t, l2p);
                unpack2(D3, d3t, d3p);

                // dot = (l1 + l2 - d_ik) / 2   (law of cosines)
                float dott = 0.5f * ((l1t + l2t) - d3t);
                float dotp = 0.5f * ((l1p + l2p) - d3p);

                float ct = dott * rsqrtf(fmaxf(l1t, ML2) * fmaxf(l2t, ML2));
                float cp = dotp * rsqrtf(fmaxf(l1p, ML2) * fmaxf(l2p, ML2));
                float sint = sqrt_approx(fmaxf(1.0f - ct * ct, 0.0f));
                float sinp = sqrt_approx(fmaxf(1.0f - cp * cp, 0.0f));
                ct = fminf(fmaxf(ct, lo), hi);
                cp = fminf(fmaxf(cp, lo), hi);

                bool ok = okb && (l1t > ML2) && (l2t > ML2) && (l1p > ML2) && (l2p > ML2);

                float dc = cp - ct;
                float ds = sinp - sint;
                if (ok) { anum += dc * dc + ds * ds; aden += 1.0f; }
            }
        }
        float ang = anum * rcp_approx(aden + EPSV);

        acc = atom + ang;
    }

    // ---------------- block reduction ----------------
#pragma unroll
    for (int off = 16; off > 0; off >>= 1)
        acc += __shfl_down_sync(0xffffffffu, acc, off);

    if ((tid & 31) == 0) warpsum[tid >> 5] = acc;
    __syncthreads();
    if (tid == 0) {
        float s = 0.0f;
#pragma unroll
        for (int w = 0; w < BLK / 32; w++) s += warpsum[w];
        atomicAdd(out, s * (1.0f / (float)NROWS));
    }
}

extern "C" void kernel_launch(void* const* d_in, const int* in_sizes, int n_in,
                              void* d_out, int out_size)
{
    const float* x      = (const float*)d_in[0];
    const float* yt     = (const float*)d_in[1];
    const float* yp     = (const float*)d_in[2];
    const float* mk     = (const float*)d_in[3];
    const int*   trip   = (const int*)d_in[4];
    const int*   tvalid = (const int*)d_in[5];
    float* out = (float*)d_out;

    zero_out_kernel<<<1, 1>>>(out);
    const int grid = (NROWS + BLK - 1) / BLK;
    loss_kernel<<<grid, BLK>>>(x, yt, yp, mk, trip, tvalid, out);
}

// round 16
// speedup vs baseline: 1.2310x; 1.2310x over previous
#include <cuda_runtime.h>
#include <math.h>

#define NROWS 500000
#define NA 5
#define TT 8
#define NE 18
#define MB 4
#define EPSV 1e-8f
#define ML2 (0.02f * 0.02f)
#define BLK 128
#define NCLS (NE * MB * TT)   // 576

typedef unsigned long long u64;

__device__ unsigned g_pk[NCLS];   // packed table, built once per launch sequence

__device__ __forceinline__ float sqrt_approx(float a) {
    float r; asm("sqrt.approx.f32 %0, %1;" : "=f"(r) : "f"(a)); return r;
}
__device__ __forceinline__ float rcp_approx(float a) {
    float r; asm("rcp.approx.f32 %0, %1;" : "=f"(r) : "f"(a)); return r;
}

// ---- packed f32x2 helpers ----
__device__ __forceinline__ u64 add2(u64 a, u64 b) {
    u64 r; asm("add.rn.f32x2 %0, %1, %2;" : "=l"(r) : "l"(a), "l"(b)); return r;
}
__device__ __forceinline__ u64 mul2(u64 a, u64 b) {
    u64 r; asm("mul.rn.f32x2 %0, %1, %2;" : "=l"(r) : "l"(a), "l"(b)); return r;
}
__device__ __forceinline__ u64 fma2(u64 a, u64 b, u64 c) {
    u64 r; asm("fma.rn.f32x2 %0, %1, %2, %3;" : "=l"(r) : "l"(a), "l"(b), "l"(c)); return r;
}
__device__ __forceinline__ u64 neg2(u64 a) { return a ^ 0x8000000080000000ULL; }
__device__ __forceinline__ void unpack2(u64 v, float& lo, float& hi) {
    asm("mov.b64 {%0, %1}, %2;" : "=f"(lo), "=f"(hi) : "l"(v));
}

// pair index for 5 atoms: (a<b) -> 0..9 ; a==b -> 10 (zero slot)
__device__ __forceinline__ int pidx(int a, int b) {
    if (a == b) return 10;
    int lo = min(a, b), hi = max(a, b);
    return lo * 4 - (lo * (lo - 1)) / 2 + (hi - lo - 1);
}

// one-time prep: zero the output and pack the triplet table
__global__ void prep_kernel(const int* __restrict__ trip,
                            const int* __restrict__ tvalid,
                            float* __restrict__ out)
{
    const int e = blockIdx.x * blockDim.x + threadIdx.x;
    if (e == 0) out[0] = 0.0f;
    if (e < NCLS) {
        const int i0 = trip[3 * e + 0];
        const int i1 = trip[3 * e + 1];
        const int i2 = trip[3 * e + 2];
        const int v  = tvalid[e];
        const unsigned ok = (i0 >= 0 && i1 >= 0 && i2 >= 0 && v > 0) ? 1u : 0u;
        const int ii = max(i0, 0);
        const int jj = max(i1, 0);
        const int kk = max(i2, 0);
        const unsigned p1 = (unsigned)pidx(ii, jj);   // |i-j|^2
        const unsigned p2 = (unsigned)pidx(kk, jj);   // |k-j|^2
        const unsigned p3 = (unsigned)pidx(ii, kk);   // |i-k|^2
        g_pk[e] = (unsigned)ii | ((unsigned)jj << 3) | ((unsigned)kk << 6)
                | (p1 << 9) | (p2 << 13) | (p3 << 17) | (ok << 21);
    }
}

__global__ void __launch_bounds__(BLK, 8) loss_kernel(
    const float* __restrict__ x,
    const float* __restrict__ yt,
    const float* __restrict__ yp,
    const float* __restrict__ mk,
    float* __restrict__ out)
{
    __shared__ __align__(16) unsigned s_pk[NCLS];    // 2.3 KB
    __shared__ __align__(16) float2  s_tp[BLK * 15]; // staged {t,p}; reused per-thread for pair D^2
    __shared__ float warpsum[BLK / 32];

    const int tid  = threadIdx.x;
    const int row0 = blockIdx.x * BLK;
    const int cnt  = min(BLK, NROWS - row0);
    const bool live = (tid < cnt);
    const int row  = row0 + tid;

    // -------- early per-thread mask load (binary 0/1 -> 15-bit mask) --------
    unsigned mb = 0;
    if (live) {
        const float* mrow = mk + (size_t)row * 15;
#pragma unroll
        for (int e = 0; e < 15; e++)
            mb |= (mrow[e] > 0.0f ? 1u : 0u) << e;
    }
    float gate = 0.0f, bd = 0.0f;
    if (live) {
        const float2 xg = *(const float2*)(x + (size_t)row * 38 + 36);
        bd = xg.x; gate = xg.y;
    }

    // -------- copy prepacked table (plain copy, no ALU) --------
#pragma unroll
    for (int e = tid; e < NCLS; e += BLK) s_pk[e] = g_pk[e];

    // -------- stage y_true/y_pred interleaved --------
    if (cnt == BLK) {
        const float2* gt2 = (const float2*)(yt + (size_t)row0 * 15);
        const float2* gp2 = (const float2*)(yp + (size_t)row0 * 15);
        float4* d4 = (float4*)s_tp;
#pragma unroll
        for (int k = 0; k < 8; k++) {
            int i = tid + k * BLK;
            if (i < 960) {
                float2 a = gt2[i];
                float2 b = gp2[i];
                d4[i] = make_float4(a.x, b.x, a.y, b.y);  // s_tp[2i], s_tp[2i+1]
            }
        }
    } else {
        const int tot = cnt * 15;
        const float* gt = yt + (size_t)row0 * 15;
        const float* gp = yp + (size_t)row0 * 15;
        for (int i = tid; i < tot; i += BLK)
            s_tp[i] = make_float2(gt[i], gp[i]);
    }
    __syncthreads();

    float acc = 0.0f;

    if (live) {
        u64* myp = (u64*)(s_tp + tid * 15);   // thread-PRIVATE slice

        // ---- load own 15 {t,p} u64 into registers ----
        u64 q[15];
#pragma unroll
        for (int c = 0; c < 15; c++) q[c] = myp[c];

        // ---------------- atom MSE (from registers) ----------------
        unsigned avmask = 0;
        float num = 0.0f;
#pragma unroll
        for (int a = 0; a < NA; a++) {
            float t0, p0, t1, p1, t2, p2;
            unpack2(q[3 * a + 0], t0, p0);
            unpack2(q[3 * a + 1], t1, p1);
            unpack2(q[3 * a + 2], t2, p2);
            float d0 = t0 - p0, d1 = t1 - p1, d2 = t2 - p2;
            unsigned g = (mb >> (3 * a)) & 7u;
            num += ((g & 1u) ? d0 * d0 : 0.0f)
                 + ((g & 2u) ? d1 * d1 : 0.0f)
                 + ((g & 4u) ? d2 * d2 : 0.0f);
            avmask |= (g ? 1u : 0u) << a;
        }
        float atom = num * rcp_approx((float)__popc(avmask) + EPSV);

        // ---- precompute 10 packed pair squared-distances into own slice ----
        {
            const int PA[10] = {0,0,0,0,1,1,1,2,2,3};
            const int PB[10] = {1,2,3,4,2,3,4,3,4,4};
#pragma unroll
            for (int pr = 0; pr < 10; pr++) {
                const int a = PA[pr], b = PB[pr];
                u64 dx = add2(q[a * 3 + 0], neg2(q[b * 3 + 0]));
                u64 dy = add2(q[a * 3 + 1], neg2(q[b * 3 + 1]));
                u64 dz = add2(q[a * 3 + 2], neg2(q[b * 3 + 2]));
                myp[pr] = fma2(dz, dz, fma2(dy, dy, mul2(dx, dx)));
            }
            myp[10] = 0ULL;   // zero slot for degenerate pairs
        }

        // ---------------- angle loss via law of cosines ----------------
        if (!isfinite(gate)) gate = 0.0f;
        int rid = (int)rintf(gate) - 1;
        rid = min(max(rid, 0), NE - 1);
        if (!isfinite(bd)) bd = 0.0f;
        int bid = min(max((int)rintf(bd), 0), MB - 1);

        const int base = (rid * MB + bid) * TT;      // multiple of 8 -> 32B aligned
        const uint4* pkp = (const uint4*)(s_pk + base);

        const float lo = -1.0f + 1e-6f, hi = 1.0f - 1e-6f;
        float anum = 0.0f, aden = 0.0f;

#pragma unroll
        for (int h = 0; h < 2; h++) {
            const uint4 pk4 = pkp[h];
            const unsigned pkw[4] = { pk4.x, pk4.y, pk4.z, pk4.w };
#pragma unroll
            for (int e = 0; e < 4; e++) {
                const unsigned pk = pkw[e];
                const int ii = pk & 7;
                const int jj = (pk >> 3) & 7;
                const int kk = (pk >> 6) & 7;
                unsigned okb = (pk >> 21) & (avmask >> ii) & (avmask >> jj) & (avmask >> kk) & 1u;

                // 3 LDS.64: packed {true,pred} pair distances
                u64 L1 = myp[(pk >> 9)  & 15];   // |i-j|^2
                u64 L2 = myp[(pk >> 13) & 15];   // |k-j|^2
                u64 D3 = myp[(pk >> 17) & 15];   // |i-k|^2

                float l1t, l1p, l2t, l2p, d3t, d3p;
                unpack2(L1, l1t, l1p);
                unpack2(L2, l2t, l2p);
                unpack2(D3, d3t, d3p);

                // dot = (l1 + l2 - d_ik) / 2   (law of cosines)
                float dott = 0.5f * ((l1t + l2t) - d3t);
                float dotp = 0.5f * ((l1p + l2p) - d3p);

                float ct = dott * rsqrtf(fmaxf(l1t, ML2) * fmaxf(l2t, ML2));
                float cp = dotp * rsqrtf(fmaxf(l1p, ML2) * fmaxf(l2p, ML2));
                float sint = sqrt_approx(fmaxf(1.0f - ct * ct, 0.0f));
                float sinp = sqrt_approx(fmaxf(1.0f - cp * cp, 0.0f));
                ct = fminf(fmaxf(ct, lo), hi);
                cp = fminf(fmaxf(cp, lo), hi);

                bool ok = okb && (l1t > ML2) && (l2t > ML2) && (l1p > ML2) && (l2p > ML2);

                float dc = cp - ct;
                float ds = sinp - sint;
                if (ok) { anum += dc * dc + ds * ds; aden += 1.0f; }
            }
        }
        float ang = anum * rcp_approx(aden + EPSV);

        acc = atom + ang;
    }

    // ---------------- block reduction ----------------
#pragma unroll
    for (int off = 16; off > 0; off >>= 1)
        acc += __shfl_down_sync(0xffffffffu, acc, off);

    if ((tid & 31) == 0) warpsum[tid >> 5] = acc;
    __syncthreads();
    if (tid == 0) {
        float s = 0.0f;
#pragma unroll
        for (int w = 0; w < BLK / 32; w++) s += warpsum[w];
        atomicAdd(out, s * (1.0f / (float)NROWS));
    }
}

extern "C" void kernel_launch(void* const* d_in, const int* in_sizes, int n_in,
                              void* d_out, int out_size)
{
    const float* x      = (const float*)d_in[0];
    const float* yt     = (const float*)d_in[1];
    const float* yp     = (const float*)d_in[2];
    const float* mk     = (const float*)d_in[3];
    const int*   trip   = (const int*)d_in[4];
    const int*   tvalid = (const int*)d_in[5];
    float* out = (float*)d_out;

    prep_kernel<<<(NCLS + BLK - 1) / BLK, BLK>>>(trip, tvalid, out);
    const int grid = (NROWS + BLK - 1) / BLK;
    loss_kernel<<<grid, BLK>>>(x, yt, yp, mk, out);
}